// round 13
// baseline (speedup 1.0000x reference)
#include <cuda_runtime.h>
#include <math.h>

#define NMAX 500000
#define CCH  64
#define KTAP 27

#define NC0 4096
#define NC1 32768
#define NC2 131072
#define NCT (NC0 + NC1 + NC2)

// ---------------------------------------------------------------------------
// Device scratch
// ---------------------------------------------------------------------------
__device__ float  g_bufA[NMAX * CCH];
__device__ float  g_bufB[NMAX * CCH];
__device__ float  g_bufC[NMAX * CCH];
__device__ float  g_sumA[NCT * CCH];
__device__ float  g_denA[NCT * CCH];
__device__ float  g_pfA[NCT * CCH];
__device__ float  g_cntA[NCT];
__device__ float  g_adpw[NMAX * 3];
__device__ float  g_S[CCH * CCH];
__device__ float  g_m[CCH];
__device__ float  g_bnc[8 * 128];
__device__ double g_stats[2 * CCH];

// ---------------------------------------------------------------------------
// Helpers
// ---------------------------------------------------------------------------
__device__ __forceinline__ unsigned f2tf32(float x) {
    unsigned r;
    asm("cvt.rna.tf32.f32 %0, %1;" : "=r"(r) : "f"(x));
    return r;
}
__device__ __forceinline__ float f2tf32f(float x) {
    unsigned r = f2tf32(x);
    return __uint_as_float(r);
}

__device__ __forceinline__ void red2(float* addr, float v0, float v1) {
    asm volatile("red.global.add.v2.f32 [%0], {%1, %2};"
                 :: "l"(addr), "f"(v0), "f"(v1) : "memory");
}
__device__ __forceinline__ void red4(float* addr, float v0, float v1,
                                     float v2, float v3) {
    asm volatile("red.global.add.v4.f32 [%0], {%1, %2, %3, %4};"
                 :: "l"(addr), "f"(v0), "f"(v1), "f"(v2), "f"(v3) : "memory");
}

// exchange a float pair with lane (t^1); both lanes converged
__device__ __forceinline__ float2 shfl_xor1_f2(float a, float b) {
    unsigned lo = __shfl_xor_sync(0xffffffffu, __float_as_uint(a), 1);
    unsigned hi = __shfl_xor_sync(0xffffffffu, __float_as_uint(b), 1);
    return make_float2(__uint_as_float(lo), __uint_as_float(hi));
}

__device__ __forceinline__ void mma_tf32(float d[4], const unsigned a[4],
                                         const unsigned b[2]) {
    asm volatile(
        "mma.sync.aligned.m16n8k8.row.col.f32.tf32.tf32.f32 "
        "{%0,%1,%2,%3}, {%4,%5,%6,%7}, {%8,%9}, {%0,%1,%2,%3};"
        : "+f"(d[0]), "+f"(d[1]), "+f"(d[2]), "+f"(d[3])
        : "r"(a[0]), "r"(a[1]), "r"(a[2]), "r"(a[3]), "r"(b[0]), "r"(b[1]));
}

__device__ __forceinline__ void cpa16(void* smem_dst, const void* gsrc, int sz) {
    unsigned d = (unsigned)__cvta_generic_to_shared(smem_dst);
    asm volatile("cp.async.cg.shared.global [%0], [%1], 16, %2;\n"
                 :: "r"(d), "l"(gsrc), "r"(sz));
}
__device__ __forceinline__ void cpa_commit() {
    asm volatile("cp.async.commit_group;\n");
}
template <int N>
__device__ __forceinline__ void cpa_wait() {
    asm volatile("cp.async.wait_group %0;\n" :: "n"(N));
}

// ---------------------------------------------------------------------------
// smem layouts
// ---------------------------------------------------------------------------
#define XST 68
#define SM_XS (128 * XST)
#define SM_WS (64 * XST)
#define GEMM_SM_FLOATS (SM_XS + SM_WS + 320)
#define GEMM_SM_BYTES  (GEMM_SM_FLOATS * 4)

#define LWS_SM_FLOATS (SM_XS + SM_WS + 256)
#define LWS_SM_BYTES  (LWS_SM_FLOATS * 4)

#define T3_SM_FLOATS (2 * SM_XS + SM_WS)
#define T3_SM_BYTES  (T3_SM_FLOATS * 4)

#define CSM_X (128 * XST)
#define CSM_W (64 * XST)
#define CONV_SM_FLOATS (2 * CSM_X + 2 * CSM_W + 160)
#define CONV_SM_BYTES  (CONV_SM_FLOATS * 4)

// ---------------------------------------------------------------------------
// Common GEMM building blocks (128-thread mid kernels)
// ---------------------------------------------------------------------------
__device__ __forceinline__ void load_x_plain(unsigned* XSu,
                                             const float* __restrict__ X,
                                             int base, int tid, int nrows)
{
    int n = base + tid;
    if (n < nrows) {
        const float4* src = (const float4*)(X + (size_t)n * 64);
#pragma unroll
        for (int c4 = 0; c4 < 16; c4++) {
            float4 v = src[c4];
            uint4 u;
            u.x = f2tf32(v.x); u.y = f2tf32(v.y);
            u.z = f2tf32(v.z); u.w = f2tf32(v.w);
            *(uint4*)&XSu[tid * XST + c4 * 4] = u;
        }
    } else {
        uint4 z = make_uint4(0, 0, 0, 0);
#pragma unroll
        for (int c4 = 0; c4 < 16; c4++)
            *(uint4*)&XSu[tid * XST + c4 * 4] = z;
    }
}

__device__ __forceinline__ void load_w_tile(unsigned* WSu,
                                            const float* __restrict__ W, int tid)
{
    int r = tid >> 1, h = (tid & 1) * 32;
    const float4* src = (const float4*)(W + r * 64 + h);
#pragma unroll
    for (int c4 = 0; c4 < 8; c4++) {
        float4 v = src[c4];
        uint4 u;
        u.x = f2tf32(v.x); u.y = f2tf32(v.y);
        u.z = f2tf32(v.z); u.w = f2tf32(v.w);
        *(uint4*)&WSu[r * XST + h + c4 * 4] = u;
    }
}

__device__ __forceinline__ void mma_block(float d[2][8][4],
                                          const unsigned* XSu,
                                          const unsigned* WSu,
                                          int w, int g, int t)
{
#pragma unroll
    for (int kt = 0; kt < 8; kt++) {
        int k0 = kt * 8;
        unsigned b[8][2];
#pragma unroll
        for (int nt = 0; nt < 8; nt++) {
            b[nt][0] = WSu[(k0 + t) * XST + nt * 8 + g];
            b[nt][1] = WSu[(k0 + t + 4) * XST + nt * 8 + g];
        }
#pragma unroll
        for (int mt = 0; mt < 2; mt++) {
            int m0 = w * 32 + mt * 16;
            unsigned a[4];
            a[0] = XSu[(m0 + g) * XST + k0 + t];
            a[1] = XSu[(m0 + g + 8) * XST + k0 + t];
            a[2] = XSu[(m0 + g) * XST + k0 + t + 4];
            a[3] = XSu[(m0 + g + 8) * XST + k0 + t + 4];
#pragma unroll
            for (int nt = 0; nt < 8; nt++) mma_tf32(d[mt][nt], a, b[nt]);
        }
    }
}

__device__ __forceinline__ void zero_acc(float d[2][8][4]) {
#pragma unroll
    for (int mt = 0; mt < 2; mt++)
#pragma unroll
        for (int nt = 0; nt < 8; nt++)
#pragma unroll
            for (int i = 0; i < 4; i++) d[mt][nt][i] = 0.f;
}

// warp-split pieces for the 256-thread conv
__device__ __forceinline__ void mma_split(float d[2][4][4],
                                          const unsigned* XSu,
                                          const unsigned* WSu,
                                          int mrow0, int nbase, int g, int t)
{
#pragma unroll
    for (int kt = 0; kt < 8; kt++) {
        int k0 = kt * 8;
        unsigned b[4][2];
#pragma unroll
        for (int nt = 0; nt < 4; nt++) {
            b[nt][0] = WSu[(k0 + t) * XST + nbase + nt * 8 + g];
            b[nt][1] = WSu[(k0 + t + 4) * XST + nbase + nt * 8 + g];
        }
#pragma unroll
        for (int mt = 0; mt < 2; mt++) {
            int m0 = mrow0 + mt * 16;
            unsigned a[4];
            a[0] = XSu[(m0 + g) * XST + k0 + t];
            a[1] = XSu[(m0 + g + 8) * XST + k0 + t];
            a[2] = XSu[(m0 + g) * XST + k0 + t + 4];
            a[3] = XSu[(m0 + g + 8) * XST + k0 + t + 4];
#pragma unroll
            for (int nt = 0; nt < 4; nt++) mma_tf32(d[mt][nt], a, b[nt]);
        }
    }
}

__device__ __forceinline__ void zero_acc4(float d[2][4][4]) {
#pragma unroll
    for (int mt = 0; mt < 2; mt++)
#pragma unroll
        for (int nt = 0; nt < 4; nt++)
#pragma unroll
            for (int i = 0; i < 4; i++) d[mt][nt][i] = 0.f;
}

// ---------------------------------------------------------------------------
// lwsum (128 threads): 3 l_w GEMMs; paired red4 cluster-sum scatter.
// ---------------------------------------------------------------------------
struct LWS {
    const float* X; const float* Wbase;
    const float* Wadp; float* adp;
    float* sc0; float* sc1; float* sc2;
    float* cnt0; float* cnt1; float* cnt2;
    const int* cl0; const int* cl1; const int* cl2;
    const float* bnc;
    int nrows;
};

__global__ void __launch_bounds__(128) lwsum_k(LWS p)
{
    extern __shared__ float sm[];
    unsigned* XSu = (unsigned*)sm;
    unsigned* WSu = (unsigned*)(sm + SM_XS);
    float* wadp   = sm + SM_XS + SM_WS;

    const int tid  = threadIdx.x;
    const int base = blockIdx.x * 128;
    const int lane = tid & 31, w = tid >> 5, g = lane >> 2, t = lane & 3;
    const bool lead = ((t & 1) == 0);

    if (tid < 96) ((float2*)wadp)[tid] = ((const float2*)p.Wadp)[tid];
    __syncthreads();

    int n = base + tid;
    if (n < p.nrows) {
        const float4* src = (const float4*)(p.X + (size_t)n * 64);
        float l0 = 0.f, l1 = 0.f, l2 = 0.f;
#pragma unroll
        for (int c4 = 0; c4 < 16; c4++) {
            float4 v = src[c4];
            int c = c4 * 4;
            l0 += v.x * wadp[(c + 0) * 3 + 0] + v.y * wadp[(c + 1) * 3 + 0] +
                  v.z * wadp[(c + 2) * 3 + 0] + v.w * wadp[(c + 3) * 3 + 0];
            l1 += v.x * wadp[(c + 0) * 3 + 1] + v.y * wadp[(c + 1) * 3 + 1] +
                  v.z * wadp[(c + 2) * 3 + 1] + v.w * wadp[(c + 3) * 3 + 1];
            l2 += v.x * wadp[(c + 0) * 3 + 2] + v.y * wadp[(c + 1) * 3 + 2] +
                  v.z * wadp[(c + 2) * 3 + 2] + v.w * wadp[(c + 3) * 3 + 2];
            uint4 u;
            u.x = f2tf32(v.x); u.y = f2tf32(v.y);
            u.z = f2tf32(v.z); u.w = f2tf32(v.w);
            *(uint4*)&XSu[tid * XST + c4 * 4] = u;
        }
        float m = fmaxf(l0, fmaxf(l1, l2));
        float e0 = expf(l0 - m), e1 = expf(l1 - m), e2 = expf(l2 - m);
        float inv = 1.f / (e0 + e1 + e2);
        p.adp[(size_t)n * 3 + 0] = e0 * inv;
        p.adp[(size_t)n * 3 + 1] = e1 * inv;
        p.adp[(size_t)n * 3 + 2] = e2 * inv;
        atomicAdd(&p.cnt0[p.cl0[n]], 1.f);
        atomicAdd(&p.cnt1[p.cl1[n]], 1.f);
        atomicAdd(&p.cnt2[p.cl2[n]], 1.f);
    } else {
        uint4 z = make_uint4(0, 0, 0, 0);
#pragma unroll
        for (int c4 = 0; c4 < 16; c4++)
            *(uint4*)&XSu[tid * XST + c4 * 4] = z;
    }

    float* scs[3]  = {p.sc0, p.sc1, p.sc2};
    const int* cls[3] = {p.cl0, p.cl1, p.cl2};

    float d[2][8][4];
#pragma unroll
    for (int s = 0; s < 3; s++) {
        __syncthreads();
        load_w_tile(WSu, p.Wbase + s * 4096, tid);
        __syncthreads();
        zero_acc(d);
        mma_block(d, XSu, WSu, w, g, t);

        const float* bc = p.bnc + s * 128;
        float* sc = scs[s];
        const int* cl = cls[s];
        int r0a[2], r1a[2], cr0a[2], cr1a[2];
#pragma unroll
        for (int mt = 0; mt < 2; mt++) {
            r0a[mt] = base + w * 32 + mt * 16 + g;
            r1a[mt] = r0a[mt] + 8;
            cr0a[mt] = (r0a[mt] < p.nrows) ? cl[r0a[mt]] : 0;
            cr1a[mt] = (r1a[mt] < p.nrows) ? cl[r1a[mt]] : 0;
        }
#pragma unroll
        for (int nt = 0; nt < 8; nt++) {
            int c0 = nt * 8 + 2 * t;
            float s0 = __ldg(&bc[c0]),      s1 = __ldg(&bc[c0 + 1]);
            float h0 = __ldg(&bc[64 + c0]), h1 = __ldg(&bc[64 + c0 + 1]);
#pragma unroll
            for (int mt = 0; mt < 2; mt++) {
                float v0 = fmaxf(d[mt][nt][0] * s0 + h0, 0.f);
                float v1 = fmaxf(d[mt][nt][1] * s1 + h1, 0.f);
                float2 q = shfl_xor1_f2(v0, v1);
                if (lead && r0a[mt] < p.nrows)
                    red4(&sc[(size_t)cr0a[mt] * 64 + c0], v0, v1, q.x, q.y);
                float v2 = fmaxf(d[mt][nt][2] * s0 + h0, 0.f);
                float v3 = fmaxf(d[mt][nt][3] * s1 + h1, 0.f);
                float2 q2 = shfl_xor1_f2(v2, v3);
                if (lead && r1a[mt] < p.nrows)
                    red4(&sc[(size_t)cr1a[mt] * 64 + c0], v2, v3, q2.x, q2.y);
            }
        }
    }
}

// ---------------------------------------------------------------------------
// t3comb (128 threads): paired float4 exppw store + red4 denom scatter
// ---------------------------------------------------------------------------
struct T3P {
    const float* X;
    const float* Wlw; const float* Ww;
    const float* bnc;
    const float* sum0; const float* sum1; const float* sum2;
    const float* cnt0; const float* cnt1; const float* cnt2;
    float* den0; float* den1; float* den2;
    float* out0; float* out1; float* out2;
    const int* cl0; const int* cl1; const int* cl2;
    int nrows;
};

__global__ void __launch_bounds__(128) t3comb_k(T3P p)
{
    extern __shared__ float sm[];
    unsigned* XSu  = (unsigned*)sm;
    unsigned* XS2u = (unsigned*)(sm + SM_XS);
    unsigned* WSu  = (unsigned*)(sm + 2 * SM_XS);

    const int tid  = threadIdx.x;
    const int base = blockIdx.x * 128;
    const int lane = tid & 31, w = tid >> 5, g = lane >> 2, t = lane & 3;
    const bool lead = ((t & 1) == 0);

    load_x_plain(XSu, p.X, base, tid, p.nrows);

    const float* sums[3] = {p.sum0, p.sum1, p.sum2};
    const float* cnts[3] = {p.cnt0, p.cnt1, p.cnt2};
    float* dens[3] = {p.den0, p.den1, p.den2};
    float* outs[3] = {p.out0, p.out1, p.out2};
    const int* cls[3] = {p.cl0, p.cl1, p.cl2};

    float d[2][8][4];
#pragma unroll
    for (int s = 0; s < 3; s++) {
        __syncthreads();
        load_w_tile(WSu, p.Wlw + s * 4096, tid);
        __syncthreads();
        zero_acc(d);
        mma_block(d, XSu, WSu, w, g, t);

        const float* bc  = p.bnc + s * 128;
        const float* sum = sums[s];
        const float* cnt = cnts[s];
        const int* cl = cls[s];
#pragma unroll
        for (int mt = 0; mt < 2; mt++) {
            int lr0 = w * 32 + mt * 16 + g;
            int lr1 = lr0 + 8;
            int r0 = base + lr0, r1 = base + lr1;
            if (r0 < p.nrows) {
                int c = cl[r0];
                float minv = 1.f / fmaxf(cnt[c], 1.f);
                const float* mrow = sum + (size_t)c * 64;
#pragma unroll
                for (int nt = 0; nt < 8; nt++) {
                    int c0 = nt * 8 + 2 * t;
                    float v0 = fmaxf(d[mt][nt][0] * __ldg(&bc[c0]) + __ldg(&bc[64 + c0]), 0.f);
                    float v1 = fmaxf(d[mt][nt][1] * __ldg(&bc[c0 + 1]) + __ldg(&bc[64 + c0 + 1]), 0.f);
                    uint2 u;
                    u.x = f2tf32(v0 - mrow[c0] * minv);
                    u.y = f2tf32(v1 - mrow[c0 + 1] * minv);
                    *(uint2*)&XS2u[lr0 * XST + c0] = u;
                }
            } else {
#pragma unroll
                for (int nt = 0; nt < 8; nt++)
                    *(uint2*)&XS2u[lr0 * XST + nt * 8 + 2 * t] = make_uint2(0, 0);
            }
            if (r1 < p.nrows) {
                int c = cl[r1];
                float minv = 1.f / fmaxf(cnt[c], 1.f);
                const float* mrow = sum + (size_t)c * 64;
#pragma unroll
                for (int nt = 0; nt < 8; nt++) {
                    int c0 = nt * 8 + 2 * t;
                    float v2 = fmaxf(d[mt][nt][2] * __ldg(&bc[c0]) + __ldg(&bc[64 + c0]), 0.f);
                    float v3 = fmaxf(d[mt][nt][3] * __ldg(&bc[c0 + 1]) + __ldg(&bc[64 + c0 + 1]), 0.f);
                    uint2 u;
                    u.x = f2tf32(v2 - mrow[c0] * minv);
                    u.y = f2tf32(v3 - mrow[c0 + 1] * minv);
                    *(uint2*)&XS2u[lr1 * XST + c0] = u;
                }
            } else {
#pragma unroll
                for (int nt = 0; nt < 8; nt++)
                    *(uint2*)&XS2u[lr1 * XST + nt * 8 + 2 * t] = make_uint2(0, 0);
            }
        }
        __syncthreads();
        load_w_tile(WSu, p.Ww + s * 4096, tid);
        __syncthreads();
        zero_acc(d);
        mma_block(d, XS2u, WSu, w, g, t);

        float* out = outs[s];
        float* den = dens[s];
#pragma unroll
        for (int mt = 0; mt < 2; mt++) {
            int r0 = base + w * 32 + mt * 16 + g;
            int r1 = r0 + 8;
            int c0i = (r0 < p.nrows) ? cl[r0] : 0;
            int c1i = (r1 < p.nrows) ? cl[r1] : 0;
#pragma unroll
            for (int nt = 0; nt < 8; nt++) {
                int c0 = nt * 8 + 2 * t;
                float e0 = expf(d[mt][nt][0]);
                float e1 = expf(d[mt][nt][1]);
                float2 q = shfl_xor1_f2(e0, e1);
                if (lead && r0 < p.nrows) {
                    *(float4*)(out + (size_t)r0 * 64 + c0) = make_float4(e0, e1, q.x, q.y);
                    red4(&den[(size_t)c0i * 64 + c0], e0, e1, q.x, q.y);
                }
                float e2 = expf(d[mt][nt][2]);
                float e3 = expf(d[mt][nt][3]);
                float2 q2 = shfl_xor1_f2(e2, e3);
                if (lead && r1 < p.nrows) {
                    *(float4*)(out + (size_t)r1 * 64 + c0) = make_float4(e2, e3, q2.x, q2.y);
                    red4(&den[(size_t)c1i * 64 + c0], e2, e3, q2.x, q2.y);
                }
            }
        }
    }
}

// ---------------------------------------------------------------------------
// projcomb (128 threads): paired red4 pf scatter (+float4 PW/den loads),
// paired float4 f_last store
// ---------------------------------------------------------------------------
struct PJP {
    const float* X; const float* Wbase;
    const float* PW0; const float* PW1; const float* PW2;
    const float* dn0; const float* dn1; const float* dn2;
    float* pf0; float* pf1; float* pf2;
    const int* cl0; const int* cl1; const int* cl2;
    float* flast;
    const float* bnc;
    int nrows;
};

__global__ void __launch_bounds__(128) projcomb_k(PJP p)
{
    extern __shared__ float sm[];
    unsigned* XSu = (unsigned*)sm;
    unsigned* WSu = (unsigned*)(sm + SM_XS);

    const int tid  = threadIdx.x;
    const int base = blockIdx.x * 128;
    const int lane = tid & 31, w = tid >> 5, g = lane >> 2, t = lane & 3;
    const bool lead = ((t & 1) == 0);

    load_x_plain(XSu, p.X, base, tid, p.nrows);

    const float* PWs[3] = {p.PW0, p.PW1, p.PW2};
    const float* dns[3] = {p.dn0, p.dn1, p.dn2};
    float* pfs[3] = {p.pf0, p.pf1, p.pf2};
    const int* cls[3] = {p.cl0, p.cl1, p.cl2};

    float d[2][8][4];
#pragma unroll
    for (int s = 0; s < 4; s++) {
        __syncthreads();
        load_w_tile(WSu, p.Wbase + s * 4096, tid);
        __syncthreads();
        zero_acc(d);
        mma_block(d, XSu, WSu, w, g, t);

        const float* bc = p.bnc + (3 + s) * 128;
        if (s < 3) {
            const float* PW = PWs[s];
            const float* dn = dns[s];
            float* pf = pfs[s];
            const int* cl = cls[s];
            int r0a[2], r1a[2], cr0a[2], cr1a[2];
#pragma unroll
            for (int mt = 0; mt < 2; mt++) {
                r0a[mt] = base + w * 32 + mt * 16 + g;
                r1a[mt] = r0a[mt] + 8;
                cr0a[mt] = (r0a[mt] < p.nrows) ? cl[r0a[mt]] : 0;
                cr1a[mt] = (r1a[mt] < p.nrows) ? cl[r1a[mt]] : 0;
            }
#pragma unroll
            for (int nt = 0; nt < 8; nt++) {
                int c0 = nt * 8 + 2 * t;
                float s0 = __ldg(&bc[c0]),      s1 = __ldg(&bc[c0 + 1]);
                float h0 = __ldg(&bc[64 + c0]), h1 = __ldg(&bc[64 + c0 + 1]);
#pragma unroll
                for (int mt = 0; mt < 2; mt++) {
                    float v0 = fmaxf(d[mt][nt][0] * s0 + h0, 0.f);
                    float v1 = fmaxf(d[mt][nt][1] * s1 + h1, 0.f);
                    float2 q = shfl_xor1_f2(v0, v1);
                    if (lead && r0a[mt] < p.nrows) {
                        float4 pw = *(const float4*)(PW + (size_t)r0a[mt] * 64 + c0);
                        float4 de = *(const float4*)(dn + (size_t)cr0a[mt] * 64 + c0);
                        red4(&pf[(size_t)cr0a[mt] * 64 + c0],
                             v0  * (pw.x / (de.x + 1e-6f)),
                             v1  * (pw.y / (de.y + 1e-6f)),
                             q.x * (pw.z / (de.z + 1e-6f)),
                             q.y * (pw.w / (de.w + 1e-6f)));
                    }
                    float v2 = fmaxf(d[mt][nt][2] * s0 + h0, 0.f);
                    float v3 = fmaxf(d[mt][nt][3] * s1 + h1, 0.f);
                    float2 q2 = shfl_xor1_f2(v2, v3);
                    if (lead && r1a[mt] < p.nrows) {
                        float4 pw = *(const float4*)(PW + (size_t)r1a[mt] * 64 + c0);
                        float4 de = *(const float4*)(dn + (size_t)cr1a[mt] * 64 + c0);
                        red4(&pf[(size_t)cr1a[mt] * 64 + c0],
                             v2   * (pw.x / (de.x + 1e-6f)),
                             v3   * (pw.y / (de.y + 1e-6f)),
                             q2.x * (pw.z / (de.z + 1e-6f)),
                             q2.y * (pw.w / (de.w + 1e-6f)));
                    }
                }
            }
        } else {
#pragma unroll
            for (int mt = 0; mt < 2; mt++) {
                int r0 = base + w * 32 + mt * 16 + g;
                int r1 = r0 + 8;
#pragma unroll
                for (int nt = 0; nt < 8; nt++) {
                    int c0 = nt * 8 + 2 * t;
                    float s0 = __ldg(&bc[c0]),      s1 = __ldg(&bc[c0 + 1]);
                    float h0 = __ldg(&bc[64 + c0]), h1 = __ldg(&bc[64 + c0 + 1]);
                    float v0 = fmaxf(d[mt][nt][0] * s0 + h0, 0.f);
                    float v1 = fmaxf(d[mt][nt][1] * s1 + h1, 0.f);
                    float2 q = shfl_xor1_f2(v0, v1);
                    if (lead && r0 < p.nrows)
                        *(float4*)(p.flast + (size_t)r0 * 64 + c0) =
                            make_float4(v0, v1, q.x, q.y);
                    float v2 = fmaxf(d[mt][nt][2] * s0 + h0, 0.f);
                    float v3 = fmaxf(d[mt][nt][3] * s1 + h1, 0.f);
                    float2 q2 = shfl_xor1_f2(v2, v3);
                    if (lead && r1 < p.nrows)
                        *(float4*)(p.flast + (size_t)r1 * 64 + c0) =
                            make_float4(v2, v3, q2.x, q2.y);
                }
            }
        }
    }
}

// ---------------------------------------------------------------------------
// fuse-gemm (128 threads): paired float4 Y store
// ---------------------------------------------------------------------------
struct FSP {
    const float* X; const float* W; float* Y;
    const float* adp;
    const int *cl0, *cl1, *cl2;
    const float *pf0, *pf1, *pf2;
    int nrows;
};

__global__ void __launch_bounds__(128) fusek(FSP p)
{
    extern __shared__ float sm[];
    unsigned* XSu = (unsigned*)sm;
    unsigned* WSu = (unsigned*)(sm + SM_XS);
    float* SSUM = sm + SM_XS + SM_WS;
    float* SSQ  = SSUM + 64;

    const int tid  = threadIdx.x;
    const int base = blockIdx.x * 128;
    const int lane = tid & 31, w = tid >> 5, g = lane >> 2, t = lane & 3;
    const bool lead = ((t & 1) == 0);

    if (tid < 64) { SSUM[tid] = 0.f; SSQ[tid] = 0.f; }

    float d[2][8][4];
    zero_acc(d);

    for (int pp = 0; pp < 2; pp++) {
        __syncthreads();
        load_w_tile(WSu, p.W + pp * 4096, tid);
        int n = base + tid;
        if (n < p.nrows) {
            if (pp == 1) {
                float a0 = p.adp[(size_t)n * 3 + 0];
                float a1 = p.adp[(size_t)n * 3 + 1];
                float a2 = p.adp[(size_t)n * 3 + 2];
                const float4* q0 = (const float4*)(p.pf0 + (size_t)p.cl0[n] * 64);
                const float4* q1 = (const float4*)(p.pf1 + (size_t)p.cl1[n] * 64);
                const float4* q2 = (const float4*)(p.pf2 + (size_t)p.cl2[n] * 64);
#pragma unroll
                for (int c4 = 0; c4 < 16; c4++) {
                    float4 v0 = q0[c4], v1 = q1[c4], v2 = q2[c4];
                    uint4 u;
                    u.x = f2tf32(a0 * v0.x + a1 * v1.x + a2 * v2.x);
                    u.y = f2tf32(a0 * v0.y + a1 * v1.y + a2 * v2.y);
                    u.z = f2tf32(a0 * v0.z + a1 * v1.z + a2 * v2.z);
                    u.w = f2tf32(a0 * v0.w + a1 * v1.w + a2 * v2.w);
                    *(uint4*)&XSu[tid * XST + c4 * 4] = u;
                }
            } else {
                const float4* src = (const float4*)(p.X + (size_t)n * 64);
#pragma unroll
                for (int c4 = 0; c4 < 16; c4++) {
                    float4 v = src[c4];
                    uint4 u;
                    u.x = f2tf32(v.x); u.y = f2tf32(v.y);
                    u.z = f2tf32(v.z); u.w = f2tf32(v.w);
                    *(uint4*)&XSu[tid * XST + c4 * 4] = u;
                }
            }
        } else {
            uint4 z = make_uint4(0, 0, 0, 0);
#pragma unroll
            for (int c4 = 0; c4 < 16; c4++)
                *(uint4*)&XSu[tid * XST + c4 * 4] = z;
        }
        __syncthreads();
        mma_block(d, XSu, WSu, w, g, t);
    }
    __syncthreads();

#pragma unroll
    for (int mt = 0; mt < 2; mt++) {
        int r0 = base + w * 32 + mt * 16 + g;
        int r1 = r0 + 8;
#pragma unroll
        for (int nt = 0; nt < 8; nt++) {
            int c0 = nt * 8 + 2 * t;
            float2 q = shfl_xor1_f2(d[mt][nt][0], d[mt][nt][1]);
            if (lead && r0 < p.nrows)
                *(float4*)(p.Y + (size_t)r0 * 64 + c0) =
                    make_float4(d[mt][nt][0], d[mt][nt][1], q.x, q.y);
            float2 q2 = shfl_xor1_f2(d[mt][nt][2], d[mt][nt][3]);
            if (lead && r1 < p.nrows)
                *(float4*)(p.Y + (size_t)r1 * 64 + c0) =
                    make_float4(d[mt][nt][2], d[mt][nt][3], q2.x, q2.y);
        }
    }

#pragma unroll
    for (int nt = 0; nt < 8; nt++) {
        float s0 = 0.f, s1 = 0.f, q0 = 0.f, q1 = 0.f;
#pragma unroll
        for (int mt = 0; mt < 2; mt++) {
            int r0 = base + w * 32 + mt * 16 + g;
            if (r0 < p.nrows) {
                s0 += d[mt][nt][0]; q0 += d[mt][nt][0] * d[mt][nt][0];
                s1 += d[mt][nt][1]; q1 += d[mt][nt][1] * d[mt][nt][1];
            }
            if (r0 + 8 < p.nrows) {
                s0 += d[mt][nt][2]; q0 += d[mt][nt][2] * d[mt][nt][2];
                s1 += d[mt][nt][3]; q1 += d[mt][nt][3] * d[mt][nt][3];
            }
        }
        int c0 = nt * 8 + 2 * t;
        atomicAdd(&SSUM[c0], s0);     atomicAdd(&SSUM[c0 + 1], s1);
        atomicAdd(&SSQ[c0], q0);      atomicAdd(&SSQ[c0 + 1], q1);
    }
    __syncthreads();
    if (tid < 64) {
        atomicAdd(&g_stats[tid],      (double)SSUM[tid]);
        atomicAdd(&g_stats[64 + tid], (double)SSQ[tid]);
    }
}

// ---------------------------------------------------------------------------
// SYRK + bncoef + finalize
// ---------------------------------------------------------------------------
__global__ void __launch_bounds__(128) syrk_k(const float* __restrict__ X,
                                              float* __restrict__ S,
                                              float* __restrict__ M, int nrows)
{
    extern __shared__ float sm[];
    unsigned* XSu = (unsigned*)sm;
    const int tid  = threadIdx.x;
    const int base = blockIdx.x * 128;
    const int lane = tid & 31, w = tid >> 5, g = lane >> 2, t = lane & 3;

    load_x_plain(XSu, X, base, tid, nrows);
    __syncthreads();

    const int m0 = w * 16;
    float d[8][4];
#pragma unroll
    for (int nt = 0; nt < 8; nt++)
#pragma unroll
        for (int i = 0; i < 4; i++) d[nt][i] = 0.f;

#pragma unroll
    for (int kt = 0; kt < 16; kt++) {
        int k0 = kt * 8;
        unsigned a[4];
        a[0] = XSu[(k0 + t) * XST + m0 + g];
        a[1] = XSu[(k0 + t) * XST + m0 + g + 8];
        a[2] = XSu[(k0 + t + 4) * XST + m0 + g];
        a[3] = XSu[(k0 + t + 4) * XST + m0 + g + 8];
#pragma unroll
        for (int nt = 0; nt < 8; nt++) {
            unsigned b[2];
            b[0] = XSu[(k0 + t) * XST + nt * 8 + g];
            b[1] = XSu[(k0 + t + 4) * XST + nt * 8 + g];
            mma_tf32(d[nt], a, b);
        }
    }
#pragma unroll
    for (int nt = 0; nt < 8; nt++) {
        int c0 = nt * 8 + 2 * t;
        red2(&S[(m0 + g) * 64 + c0],     d[nt][0], d[nt][1]);
        red2(&S[(m0 + g + 8) * 64 + c0], d[nt][2], d[nt][3]);
    }
    if (tid < 64) {
        float s = 0.f;
        for (int r = 0; r < 128; r++)
            s += __uint_as_float(XSu[r * XST + tid]);
        atomicAdd(&M[tid], s);
    }
}

struct BC {
    const float* W[7];
    const float* gamma[7];
    const float* beta[7];
    float invN;
};

__global__ void bncoef_k(BC p, const float* __restrict__ S,
                         const float* __restrict__ M, float* __restrict__ bnc)
{
    __shared__ float Ss[4096];
    __shared__ float Ws[4096];
    __shared__ float ms[64];
    const int slot = blockIdx.x;
    const int j = threadIdx.x;
    const float* W = p.W[slot];
    for (int i = j; i < 4096; i += 64) {
        Ss[i] = S[i];
        Ws[i] = __uint_as_float(f2tf32(W[i]));
    }
    ms[j] = M[j];
    __syncthreads();

    float mu = 0.f, ex2 = 0.f;
    for (int c = 0; c < 64; c++) {
        float wc = Ws[c * 64 + j];
        mu += ms[c] * wc;
        float inner = 0.f;
        for (int c2 = 0; c2 < 64; c2++)
            inner += Ss[c * 64 + c2] * Ws[c2 * 64 + j];
        ex2 += wc * inner;
    }
    mu *= p.invN; ex2 *= p.invN;
    float var = ex2 - mu * mu;
    float rs = rsqrtf(var + 1e-3f);
    float scale = p.gamma[slot][j] * rs;
    bnc[slot * 128 + j]      = scale;
    bnc[slot * 128 + 64 + j] = p.beta[slot][j] - mu * scale;
}

__global__ void finalize_k(const float* __restrict__ gamma,
                           const float* __restrict__ beta, float invN)
{
    int c = threadIdx.x;
    float mu  = (float)g_stats[c] * invN;
    float ex2 = (float)g_stats[64 + c] * invN;
    float var = ex2 - mu * mu;
    float rs  = rsqrtf(var + 1e-3f);
    float scale = gamma[c] * rs;
    g_bnc[7 * 128 + c]      = scale;
    g_bnc[7 * 128 + 64 + c] = beta[c] - mu * scale;
    g_stats[c] = 0.0;
    g_stats[64 + c] = 0.0;
}

// ---------------------------------------------------------------------------
// Conv (256 threads, M/N warp split, depth-2 cp.async) — unchanged
// ---------------------------------------------------------------------------
__global__ void __launch_bounds__(256) conv27p(
    const float* __restrict__ F, const int* __restrict__ nbr,
    const float* __restrict__ Wc, float* __restrict__ Y, int nrows)
{
    extern __shared__ float sm[];
    float* XB0 = sm;
    float* XB1 = sm + CSM_X;
    float* WB0 = sm + 2 * CSM_X;
    float* WB1 = sm + 2 * CSM_X + CSM_W;
    float* SSUM = sm + 2 * CSM_X + 2 * CSM_W;
    float* SSQ  = SSUM + 64;

    const int tid  = threadIdx.x;
    const int base = blockIdx.x * 128;
    const int lane = tid & 31, wid = tid >> 5, g = lane >> 2, t = lane & 3;
    const int mrow0 = (wid & 3) * 32;
    const int nbase = (wid >> 2) * 32;

    const int xr = tid >> 1, xh = (tid & 1) * 32;
    const int xn = base + xr;
    const int wr = tid >> 2, wq = (tid & 3) * 16;

    if (tid < 64) { SSUM[tid] = 0.f; SSQ[tid] = 0.f; }

    float d[2][4][4];
    zero_acc4(d);

    auto prefetch = [&](int k, float* XB, float* WB) {
        const float* src = F;
        int sz = 0;
        if (xn < nrows) {
            int idx = __ldg(&nbr[(size_t)xn * KTAP + k]);
            src = F + (size_t)idx * 64 + xh;
            sz = 16;
        }
#pragma unroll
        for (int c4 = 0; c4 < 8; c4++)
            cpa16(XB + xr * XST + xh + c4 * 4, src + c4 * 4, sz);
        const float* ws = Wc + k * 4096 + wr * 64 + wq;
#pragma unroll
        for (int c4 = 0; c4 < 4; c4++)
            cpa16(WB + wr * XST + wq + c4 * 4, ws + c4 * 4, 16);
    };

    prefetch(0, XB0, WB0);
    cpa_commit();

    for (int k = 0; k < KTAP; k++) {
        float* XB = (k & 1) ? XB1 : XB0;
        float* WB = (k & 1) ? WB1 : WB0;
        if (k + 1 < KTAP) {
            prefetch(k + 1, (k & 1) ? XB0 : XB1, (k & 1) ? WB0 : WB1);
            cpa_commit();
            cpa_wait<1>();
        } else {
            cpa_wait<0>();
        }
        __syncthreads();
        mma_split(d, (const unsigned*)XB, (const unsigned*)WB, mrow0, nbase, g, t);
        __syncthreads();
    }

#pragma unroll
    for (int mt = 0; mt < 2; mt++) {
        int r0 = base + mrow0 + mt * 16 + g;
        int r1 = r0 + 8;
#pragma unroll
        for (int nt = 0; nt < 4; nt++) {
            int c0 = nbase + nt * 8 + 2 * t;
            if (r0 < nrows)
                *(float2*)(Y + (size_t)r0 * 64 + c0) = make_float2(d[mt][nt][0], d[mt][nt][1]);
            if (r1 < nrows)
                *(float2*)(Y + (size_t)r1 * 64 + c0) = make_float2(d[mt][nt][2], d[mt][nt][3]);
        }
    }
#pragma unroll
    for (int nt = 0; nt < 4; nt++) {
        float s0 = 0.f, s1 = 0.f, q0 = 0.f, q1 = 0.f;
#pragma unroll
        for (int mt = 0; mt < 2; mt++) {
            int r0 = base + mrow0 + mt * 16 + g;
            if (r0 < nrows) {
                s0 += d[mt][nt][0]; q0 += d[mt][nt][0] * d[mt][nt][0];
                s1 += d[mt][nt][1]; q1 += d[mt][nt][1] * d[mt][nt][1];
            }
            if (r0 + 8 < nrows) {
                s0 += d[mt][nt][2]; q0 += d[mt][nt][2] * d[mt][nt][2];
                s1 += d[mt][nt][3]; q1 += d[mt][nt][3] * d[mt][nt][3];
            }
        }
        int c0 = nbase + nt * 8 + 2 * t;
        atomicAdd(&SSUM[c0], s0);     atomicAdd(&SSUM[c0 + 1], s1);
        atomicAdd(&SSQ[c0], q0);      atomicAdd(&SSQ[c0 + 1], q1);
    }
    __syncthreads();
    if (tid < 64) {
        atomicAdd(&g_stats[tid],      (double)SSUM[tid]);
        atomicAdd(&g_stats[64 + tid], (double)SSQ[tid]);
    }
}

// ---------------------------------------------------------------------------
// Elementwise kernels
// ---------------------------------------------------------------------------
__global__ void init_k(float4* sum, float4* den, float4* pf, int n4,
                       float4* cnt, int nc4)
{
    int i = blockIdx.x * blockDim.x + threadIdx.x;
    float4 z = make_float4(0.f, 0.f, 0.f, 0.f);
    int stride = gridDim.x * blockDim.x;
    for (int j = i; j < n4; j += stride) { sum[j] = z; den[j] = z; pf[j] = z; }
    for (int j = i; j < nc4; j += stride) cnt[j] = z;
    if (i < 128) g_stats[i] = 0.0;
    if (i < 1024) ((float4*)g_S)[i] = z;
    if (i < 16)   ((float4*)g_m)[i] = z;
}

template <int OP>
__global__ void bnapply_f4(const float4* __restrict__ X,
                           const float4* __restrict__ add,
                           float4* __restrict__ out, int n)
{
    __shared__ float SC[64], SH[64];
    int tid = threadIdx.x;
    if (tid < 64) { SC[tid] = g_bnc[7 * 128 + tid]; SH[tid] = g_bnc[7 * 128 + 64 + tid]; }
    __syncthreads();
    int i = blockIdx.x * blockDim.x + tid;
    if (i >= n * 16) return;
    int c = (i & 15) * 4;
    float4 x = X[i];
    float4 y;
    y.x = x.x * SC[c]     + SH[c];
    y.y = x.y * SC[c + 1] + SH[c + 1];
    y.z = x.z * SC[c + 2] + SH[c + 2];
    y.w = x.w * SC[c + 3] + SH[c + 3];
    float4 o;
    if (OP == 0) {
        o.x = f2tf32f(fmaxf(y.x, 0.f)); o.y = f2tf32f(fmaxf(y.y, 0.f));
        o.z = f2tf32f(fmaxf(y.z, 0.f)); o.w = f2tf32f(fmaxf(y.w, 0.f));
    } else if (OP == 1) {
        float4 a = add[i];
        o.x = f2tf32f(fmaxf(y.x, 0.f) + a.x); o.y = f2tf32f(fmaxf(y.y, 0.f) + a.y);
        o.z = f2tf32f(fmaxf(y.z, 0.f) + a.z); o.w = f2tf32f(fmaxf(y.w, 0.f) + a.w);
    } else {
        float4 a = add[i];
        o.x = fmaxf(y.x + a.x, 0.f); o.y = fmaxf(y.y + a.y, 0.f);
        o.z = fmaxf(y.z + a.z, 0.f); o.w = fmaxf(y.w + a.w, 0.f);
    }
    out[i] = o;
}

// ---------------------------------------------------------------------------
// Host launcher
// ---------------------------------------------------------------------------
extern "C" void kernel_launch(void* const* d_in, const int* in_sizes, int n_in,
                              void* d_out, int out_size)
{
    const float* feat   = (const float*)d_in[0];
    const int*   cl0    = (const int*)d_in[1];
    const int*   cl1    = (const int*)d_in[2];
    const int*   cl2    = (const int*)d_in[3];
    const int*   nbr    = (const int*)d_in[4];
    const float* W_lw   = (const float*)d_in[5];
    const float* g_lw   = (const float*)d_in[6];
    const float* b_lw   = (const float*)d_in[7];
    const float* W_w    = (const float*)d_in[8];
    const float* W_proj = (const float*)d_in[9];
    const float* g_proj = (const float*)d_in[10];
    const float* b_proj = (const float*)d_in[11];
    const float* W_adp  = (const float*)d_in[12];
    const float* W_fuse = (const float*)d_in[13];
    const float* g_fuse = (const float*)d_in[14];
    const float* b_fuse = (const float*)d_in[15];
    const float* W_c1   = (const float*)d_in[16];
    const float* g_c1   = (const float*)d_in[17];
    const float* b_c1   = (const float*)d_in[18];
    const float* W_c2   = (const float*)d_in[19];
    const float* g_c2   = (const float*)d_in[20];
    const float* b_c2   = (const float*)d_in[21];

    const int   n    = in_sizes[0] / 64;
    const float invN = 1.f / (float)n;
    float* D = (float*)d_out;

    float *A, *B, *C, *sumA, *denA, *pfA, *cntA, *adpb, *Sg, *Mg, *bnc;
    cudaGetSymbolAddress((void**)&A,     g_bufA);
    cudaGetSymbolAddress((void**)&B,     g_bufB);
    cudaGetSymbolAddress((void**)&C,     g_bufC);
    cudaGetSymbolAddress((void**)&sumA,  g_sumA);
    cudaGetSymbolAddress((void**)&denA,  g_denA);
    cudaGetSymbolAddress((void**)&pfA,   g_pfA);
    cudaGetSymbolAddress((void**)&cntA,  g_cntA);
    cudaGetSymbolAddress((void**)&adpb,  g_adpw);
    cudaGetSymbolAddress((void**)&Sg,    g_S);
    cudaGetSymbolAddress((void**)&Mg,    g_m);
    cudaGetSymbolAddress((void**)&bnc,   g_bnc);

    float* sum_[3] = {sumA, sumA + (size_t)NC0 * 64, sumA + (size_t)(NC0 + NC1) * 64};
    float* den_[3] = {denA, denA + (size_t)NC0 * 64, denA + (size_t)(NC0 + NC1) * 64};
    float* pf_[3]  = {pfA,  pfA  + (size_t)NC0 * 64, pfA  + (size_t)(NC0 + NC1) * 64};
    float* cnt_[3] = {cntA, cntA + NC0, cntA + NC0 + NC1};

    cudaFuncSetAttribute(lwsum_k,    cudaFuncAttributeMaxDynamicSharedMemorySize, LWS_SM_BYTES);
    cudaFuncSetAttribute(t3comb_k,   cudaFuncAttributeMaxDynamicSharedMemorySize, T3_SM_BYTES);
    cudaFuncSetAttribute(projcomb_k, cudaFuncAttributeMaxDynamicSharedMemorySize, GEMM_SM_BYTES);
    cudaFuncSetAttribute(fusek,      cudaFuncAttributeMaxDynamicSharedMemorySize, GEMM_SM_BYTES);
    cudaFuncSetAttribute(syrk_k,     cudaFuncAttributeMaxDynamicSharedMemorySize, (SM_XS + 64) * 4);
    cudaFuncSetAttribute(conv27p,    cudaFuncAttributeMaxDynamicSharedMemorySize, CONV_SM_BYTES);

    const int GB = (n + 127) / 128;
    const int E4 = (n * 16 + 255) / 256;

    // 1. init scratch
    init_k<<<2048, 256>>>((float4*)sumA, (float4*)denA, (float4*)pfA,
                          NCT * 16, (float4*)cntA, NCT / 4);
    // 2. SYRK + BN coefficients
    syrk_k<<<GB, 128, (SM_XS + 64) * 4>>>(feat, Sg, Mg, n);
    {
        BC bc{};
        for (int i = 0; i < 3; i++) {
            bc.W[i] = W_lw + i * 4096;       bc.gamma[i] = g_lw + i * 64;       bc.beta[i] = b_lw + i * 64;
            bc.W[3 + i] = W_proj + i * 4096; bc.gamma[3 + i] = g_proj + i * 64; bc.beta[3 + i] = b_proj + i * 64;
        }
        bc.W[6] = W_proj + 3 * 4096; bc.gamma[6] = g_proj + 192; bc.beta[6] = b_proj + 192;
        bc.invN = invN;
        bncoef_k<<<7, 64>>>(bc, Sg, Mg, bnc);
    }

    // 3. lwsum
    {
        LWS p{};
        p.X = feat; p.Wbase = W_lw;
        p.Wadp = W_adp; p.adp = adpb;
        p.sc0 = sum_[0]; p.sc1 = sum_[1]; p.sc2 = sum_[2];
        p.cnt0 = cnt_[0]; p.cnt1 = cnt_[1]; p.cnt2 = cnt_[2];
        p.cl0 = cl0; p.cl1 = cl1; p.cl2 = cl2;
        p.bnc = bnc; p.nrows = n;
        lwsum_k<<<GB, 128, LWS_SM_BYTES>>>(p);
    }

    // 4. t3comb
    {
        T3P p{};
        p.X = feat; p.Wlw = W_lw; p.Ww = W_w; p.bnc = bnc;
        p.sum0 = sum_[0]; p.sum1 = sum_[1]; p.sum2 = sum_[2];
        p.cnt0 = cnt_[0]; p.cnt1 = cnt_[1]; p.cnt2 = cnt_[2];
        p.den0 = den_[0]; p.den1 = den_[1]; p.den2 = den_[2];
        p.out0 = B; p.out1 = C; p.out2 = D;
        p.cl0 = cl0; p.cl1 = cl1; p.cl2 = cl2;
        p.nrows = n;
        t3comb_k<<<GB, 128, T3_SM_BYTES>>>(p);
    }

    // 5. projcomb
    {
        PJP p{};
        p.X = feat; p.Wbase = W_proj;
        p.PW0 = B; p.PW1 = C; p.PW2 = D;
        p.dn0 = den_[0]; p.dn1 = den_[1]; p.dn2 = den_[2];
        p.pf0 = pf_[0]; p.pf1 = pf_[1]; p.pf2 = pf_[2];
        p.cl0 = cl0; p.cl1 = cl1; p.cl2 = cl2;
        p.flast = A; p.bnc = bnc; p.nrows = n;
        projcomb_k<<<GB, 128, GEMM_SM_BYTES>>>(p);
    }

    // 6. fuse
    {
        FSP p{};
        p.X = A; p.W = W_fuse; p.Y = B;
        p.adp = adpb;
        p.cl0 = cl0; p.cl1 = cl1; p.cl2 = cl2;
        p.pf0 = pf_[0]; p.pf1 = pf_[1]; p.pf2 = pf_[2];
        p.nrows = n;
        fusek<<<GB, 128, GEMM_SM_BYTES>>>(p);
    }
    finalize_k<<<1, 64>>>(g_fuse, b_fuse, invN);
    bnapply_f4<1><<<E4, 256>>>((const float4*)B, (const float4*)feat, (float4*)C, n);

    // 7. conv1 -> bn -> relu (tf32) -> B
    conv27p<<<GB, 256, CONV_SM_BYTES>>>(C, nbr, W_c1, A, n);
    finalize_k<<<1, 64>>>(g_c1, b_c1, invN);
    bnapply_f4<0><<<E4, 256>>>((const float4*)A, nullptr, (float4*)B, n);

    // 8. conv2 -> bn ; out = relu(h + fused)
    conv27p<<<GB, 256, CONV_SM_BYTES>>>(B, nbr, W_c2, A, n);
    finalize_k<<<1, 64>>>(g_c2, b_c2, invN);
    bnapply_f4<2><<<E4, 256>>>((const float4*)A, (const float4*)C, (float4*)D, n);
}

// round 14
// speedup vs baseline: 1.0593x; 1.0593x over previous
#include <cuda_runtime.h>
#include <math.h>

#define NMAX 500000
#define CCH  64
#define KTAP 27

#define NC0 4096
#define NC1 32768
#define NC2 131072
#define NCT (NC0 + NC1 + NC2)

// ---------------------------------------------------------------------------
// Device scratch
// ---------------------------------------------------------------------------
__device__ float  g_bufA[NMAX * CCH];
__device__ float  g_bufB[NMAX * CCH];
__device__ float  g_bufC[NMAX * CCH];
__device__ float  g_sumA[NCT * CCH];
__device__ float  g_denA[NCT * CCH];
__device__ float  g_pfA[NCT * CCH];
__device__ float  g_cntA[NCT];
__device__ float  g_adpw[NMAX * 3];
__device__ float  g_S[CCH * CCH];
__device__ float  g_m[CCH];
__device__ float  g_bnc[8 * 128];
__device__ double g_stats[2 * CCH];

// ---------------------------------------------------------------------------
// Helpers
// ---------------------------------------------------------------------------
__device__ __forceinline__ unsigned f2tf32(float x) {
    unsigned r;
    asm("cvt.rna.tf32.f32 %0, %1;" : "=r"(r) : "f"(x));
    return r;
}
__device__ __forceinline__ float f2tf32f(float x) {
    unsigned r = f2tf32(x);
    return __uint_as_float(r);
}

__device__ __forceinline__ void red2(float* addr, float v0, float v1) {
    asm volatile("red.global.add.v2.f32 [%0], {%1, %2};"
                 :: "l"(addr), "f"(v0), "f"(v1) : "memory");
}

__device__ __forceinline__ void mma_tf32(float d[4], const unsigned a[4],
                                         const unsigned b[2]) {
    asm volatile(
        "mma.sync.aligned.m16n8k8.row.col.f32.tf32.tf32.f32 "
        "{%0,%1,%2,%3}, {%4,%5,%6,%7}, {%8,%9}, {%0,%1,%2,%3};"
        : "+f"(d[0]), "+f"(d[1]), "+f"(d[2]), "+f"(d[3])
        : "r"(a[0]), "r"(a[1]), "r"(a[2]), "r"(a[3]), "r"(b[0]), "r"(b[1]));
}

__device__ __forceinline__ void cpa16(void* smem_dst, const void* gsrc, int sz) {
    unsigned d = (unsigned)__cvta_generic_to_shared(smem_dst);
    asm volatile("cp.async.cg.shared.global [%0], [%1], 16, %2;\n"
                 :: "r"(d), "l"(gsrc), "r"(sz));
}
__device__ __forceinline__ void cpa_commit() {
    asm volatile("cp.async.commit_group;\n");
}
template <int N>
__device__ __forceinline__ void cpa_wait() {
    asm volatile("cp.async.wait_group %0;\n" :: "n"(N));
}

// ---------------------------------------------------------------------------
// smem layouts
// ---------------------------------------------------------------------------
#define XST 68
#define SM_XS (128 * XST)
#define SM_WS (64 * XST)
#define GEMM_SM_FLOATS (SM_XS + SM_WS + 320)
#define GEMM_SM_BYTES  (GEMM_SM_FLOATS * 4)

#define LWS_SM_FLOATS (SM_XS + SM_WS + 256)
#define LWS_SM_BYTES  (LWS_SM_FLOATS * 4)

#define T3_SM_FLOATS (2 * SM_XS + SM_WS)
#define T3_SM_BYTES  (T3_SM_FLOATS * 4)

#define CSM_X (128 * XST)
#define CSM_W (64 * XST)
#define CONV_SM_FLOATS (2 * CSM_X + 2 * CSM_W + 160)
#define CONV_SM_BYTES  (CONV_SM_FLOATS * 4)

// ---------------------------------------------------------------------------
// Common GEMM building blocks (128-thread mid kernels)
// ---------------------------------------------------------------------------
__device__ __forceinline__ void load_x_plain(unsigned* XSu,
                                             const float* __restrict__ X,
                                             int base, int tid, int nrows)
{
    int n = base + tid;
    if (n < nrows) {
        const float4* src = (const float4*)(X + (size_t)n * 64);
#pragma unroll
        for (int c4 = 0; c4 < 16; c4++) {
            float4 v = src[c4];
            uint4 u;
            u.x = f2tf32(v.x); u.y = f2tf32(v.y);
            u.z = f2tf32(v.z); u.w = f2tf32(v.w);
            *(uint4*)&XSu[tid * XST + c4 * 4] = u;
        }
    } else {
        uint4 z = make_uint4(0, 0, 0, 0);
#pragma unroll
        for (int c4 = 0; c4 < 16; c4++)
            *(uint4*)&XSu[tid * XST + c4 * 4] = z;
    }
}

__device__ __forceinline__ void load_w_tile(unsigned* WSu,
                                            const float* __restrict__ W, int tid)
{
    int r = tid >> 1, h = (tid & 1) * 32;
    const float4* src = (const float4*)(W + r * 64 + h);
#pragma unroll
    for (int c4 = 0; c4 < 8; c4++) {
        float4 v = src[c4];
        uint4 u;
        u.x = f2tf32(v.x); u.y = f2tf32(v.y);
        u.z = f2tf32(v.z); u.w = f2tf32(v.w);
        *(uint4*)&WSu[r * XST + h + c4 * 4] = u;
    }
}

__device__ __forceinline__ void mma_block(float d[2][8][4],
                                          const unsigned* XSu,
                                          const unsigned* WSu,
                                          int w, int g, int t)
{
#pragma unroll
    for (int kt = 0; kt < 8; kt++) {
        int k0 = kt * 8;
        unsigned b[8][2];
#pragma unroll
        for (int nt = 0; nt < 8; nt++) {
            b[nt][0] = WSu[(k0 + t) * XST + nt * 8 + g];
            b[nt][1] = WSu[(k0 + t + 4) * XST + nt * 8 + g];
        }
#pragma unroll
        for (int mt = 0; mt < 2; mt++) {
            int m0 = w * 32 + mt * 16;
            unsigned a[4];
            a[0] = XSu[(m0 + g) * XST + k0 + t];
            a[1] = XSu[(m0 + g + 8) * XST + k0 + t];
            a[2] = XSu[(m0 + g) * XST + k0 + t + 4];
            a[3] = XSu[(m0 + g + 8) * XST + k0 + t + 4];
#pragma unroll
            for (int nt = 0; nt < 8; nt++) mma_tf32(d[mt][nt], a, b[nt]);
        }
    }
}

__device__ __forceinline__ void zero_acc(float d[2][8][4]) {
#pragma unroll
    for (int mt = 0; mt < 2; mt++)
#pragma unroll
        for (int nt = 0; nt < 8; nt++)
#pragma unroll
            for (int i = 0; i < 4; i++) d[mt][nt][i] = 0.f;
}

// warp-split pieces for the 256-thread conv
__device__ __forceinline__ void mma_split(float d[2][4][4],
                                          const unsigned* XSu,
                                          const unsigned* WSu,
                                          int mrow0, int nbase, int g, int t)
{
#pragma unroll
    for (int kt = 0; kt < 8; kt++) {
        int k0 = kt * 8;
        unsigned b[4][2];
#pragma unroll
        for (int nt = 0; nt < 4; nt++) {
            b[nt][0] = WSu[(k0 + t) * XST + nbase + nt * 8 + g];
            b[nt][1] = WSu[(k0 + t + 4) * XST + nbase + nt * 8 + g];
        }
#pragma unroll
        for (int mt = 0; mt < 2; mt++) {
            int m0 = mrow0 + mt * 16;
            unsigned a[4];
            a[0] = XSu[(m0 + g) * XST + k0 + t];
            a[1] = XSu[(m0 + g + 8) * XST + k0 + t];
            a[2] = XSu[(m0 + g) * XST + k0 + t + 4];
            a[3] = XSu[(m0 + g + 8) * XST + k0 + t + 4];
#pragma unroll
            for (int nt = 0; nt < 4; nt++) mma_tf32(d[mt][nt], a, b[nt]);
        }
    }
}

__device__ __forceinline__ void zero_acc4(float d[2][4][4]) {
#pragma unroll
    for (int mt = 0; mt < 2; mt++)
#pragma unroll
        for (int nt = 0; nt < 4; nt++)
#pragma unroll
            for (int i = 0; i < 4; i++) d[mt][nt][i] = 0.f;
}

// ---------------------------------------------------------------------------
// lwsum (128 threads): 3 l_w GEMMs off one feat tile; scatter cluster sums.
// ---------------------------------------------------------------------------
struct LWS {
    const float* X; const float* Wbase;
    const float* Wadp; float* adp;
    float* sc0; float* sc1; float* sc2;
    float* cnt0; float* cnt1; float* cnt2;
    const int* cl0; const int* cl1; const int* cl2;
    const float* bnc;
    int nrows;
};

__global__ void __launch_bounds__(128) lwsum_k(LWS p)
{
    extern __shared__ float sm[];
    unsigned* XSu = (unsigned*)sm;
    unsigned* WSu = (unsigned*)(sm + SM_XS);
    float* wadp   = sm + SM_XS + SM_WS;

    const int tid  = threadIdx.x;
    const int base = blockIdx.x * 128;
    const int lane = tid & 31, w = tid >> 5, g = lane >> 2, t = lane & 3;

    if (tid < 96) ((float2*)wadp)[tid] = ((const float2*)p.Wadp)[tid];
    __syncthreads();

    int n = base + tid;
    if (n < p.nrows) {
        const float4* src = (const float4*)(p.X + (size_t)n * 64);
        float l0 = 0.f, l1 = 0.f, l2 = 0.f;
#pragma unroll
        for (int c4 = 0; c4 < 16; c4++) {
            float4 v = src[c4];
            int c = c4 * 4;
            l0 += v.x * wadp[(c + 0) * 3 + 0] + v.y * wadp[(c + 1) * 3 + 0] +
                  v.z * wadp[(c + 2) * 3 + 0] + v.w * wadp[(c + 3) * 3 + 0];
            l1 += v.x * wadp[(c + 0) * 3 + 1] + v.y * wadp[(c + 1) * 3 + 1] +
                  v.z * wadp[(c + 2) * 3 + 1] + v.w * wadp[(c + 3) * 3 + 1];
            l2 += v.x * wadp[(c + 0) * 3 + 2] + v.y * wadp[(c + 1) * 3 + 2] +
                  v.z * wadp[(c + 2) * 3 + 2] + v.w * wadp[(c + 3) * 3 + 2];
            uint4 u;
            u.x = f2tf32(v.x); u.y = f2tf32(v.y);
            u.z = f2tf32(v.z); u.w = f2tf32(v.w);
            *(uint4*)&XSu[tid * XST + c4 * 4] = u;
        }
        float m = fmaxf(l0, fmaxf(l1, l2));
        float e0 = __expf(l0 - m), e1 = __expf(l1 - m), e2 = __expf(l2 - m);
        float inv = 1.f / (e0 + e1 + e2);
        p.adp[(size_t)n * 3 + 0] = e0 * inv;
        p.adp[(size_t)n * 3 + 1] = e1 * inv;
        p.adp[(size_t)n * 3 + 2] = e2 * inv;
        atomicAdd(&p.cnt0[p.cl0[n]], 1.f);
        atomicAdd(&p.cnt1[p.cl1[n]], 1.f);
        atomicAdd(&p.cnt2[p.cl2[n]], 1.f);
    } else {
        uint4 z = make_uint4(0, 0, 0, 0);
#pragma unroll
        for (int c4 = 0; c4 < 16; c4++)
            *(uint4*)&XSu[tid * XST + c4 * 4] = z;
    }

    float* scs[3]  = {p.sc0, p.sc1, p.sc2};
    const int* cls[3] = {p.cl0, p.cl1, p.cl2};

    float d[2][8][4];
#pragma unroll
    for (int s = 0; s < 3; s++) {
        __syncthreads();
        load_w_tile(WSu, p.Wbase + s * 4096, tid);
        __syncthreads();
        zero_acc(d);
        mma_block(d, XSu, WSu, w, g, t);

        const float* bc = p.bnc + s * 128;
        float* sc = scs[s];
        const int* cl = cls[s];
        int r0a[2], r1a[2], cr0a[2], cr1a[2];
#pragma unroll
        for (int mt = 0; mt < 2; mt++) {
            r0a[mt] = base + w * 32 + mt * 16 + g;
            r1a[mt] = r0a[mt] + 8;
            cr0a[mt] = (r0a[mt] < p.nrows) ? cl[r0a[mt]] : 0;
            cr1a[mt] = (r1a[mt] < p.nrows) ? cl[r1a[mt]] : 0;
        }
#pragma unroll
        for (int nt = 0; nt < 8; nt++) {
            int c0 = nt * 8 + 2 * t;
            float s0 = __ldg(&bc[c0]),      s1 = __ldg(&bc[c0 + 1]);
            float h0 = __ldg(&bc[64 + c0]), h1 = __ldg(&bc[64 + c0 + 1]);
#pragma unroll
            for (int mt = 0; mt < 2; mt++) {
                if (r0a[mt] < p.nrows)
                    red2(&sc[(size_t)cr0a[mt] * 64 + c0],
                         fmaxf(d[mt][nt][0] * s0 + h0, 0.f),
                         fmaxf(d[mt][nt][1] * s1 + h1, 0.f));
                if (r1a[mt] < p.nrows)
                    red2(&sc[(size_t)cr1a[mt] * 64 + c0],
                         fmaxf(d[mt][nt][2] * s0 + h0, 0.f),
                         fmaxf(d[mt][nt][3] * s1 + h1, 0.f));
            }
        }
    }
}

// ---------------------------------------------------------------------------
// t3comb (128 threads)
// ---------------------------------------------------------------------------
struct T3P {
    const float* X;
    const float* Wlw; const float* Ww;
    const float* bnc;
    const float* sum0; const float* sum1; const float* sum2;
    const float* cnt0; const float* cnt1; const float* cnt2;
    float* den0; float* den1; float* den2;
    float* out0; float* out1; float* out2;
    const int* cl0; const int* cl1; const int* cl2;
    int nrows;
};

__global__ void __launch_bounds__(128) t3comb_k(T3P p)
{
    extern __shared__ float sm[];
    unsigned* XSu  = (unsigned*)sm;
    unsigned* XS2u = (unsigned*)(sm + SM_XS);
    unsigned* WSu  = (unsigned*)(sm + 2 * SM_XS);

    const int tid  = threadIdx.x;
    const int base = blockIdx.x * 128;
    const int lane = tid & 31, w = tid >> 5, g = lane >> 2, t = lane & 3;

    load_x_plain(XSu, p.X, base, tid, p.nrows);

    const float* sums[3] = {p.sum0, p.sum1, p.sum2};
    const float* cnts[3] = {p.cnt0, p.cnt1, p.cnt2};
    float* dens[3] = {p.den0, p.den1, p.den2};
    float* outs[3] = {p.out0, p.out1, p.out2};
    const int* cls[3] = {p.cl0, p.cl1, p.cl2};

    float d[2][8][4];
#pragma unroll
    for (int s = 0; s < 3; s++) {
        __syncthreads();
        load_w_tile(WSu, p.Wlw + s * 4096, tid);
        __syncthreads();
        zero_acc(d);
        mma_block(d, XSu, WSu, w, g, t);

        const float* bc  = p.bnc + s * 128;
        const float* sum = sums[s];
        const float* cnt = cnts[s];
        const int* cl = cls[s];
#pragma unroll
        for (int mt = 0; mt < 2; mt++) {
            int lr0 = w * 32 + mt * 16 + g;
            int lr1 = lr0 + 8;
            int r0 = base + lr0, r1 = base + lr1;
            if (r0 < p.nrows) {
                int c = cl[r0];
                float minv = 1.f / fmaxf(cnt[c], 1.f);
                const float* mrow = sum + (size_t)c * 64;
#pragma unroll
                for (int nt = 0; nt < 8; nt++) {
                    int c0 = nt * 8 + 2 * t;
                    float v0 = fmaxf(d[mt][nt][0] * __ldg(&bc[c0]) + __ldg(&bc[64 + c0]), 0.f);
                    float v1 = fmaxf(d[mt][nt][1] * __ldg(&bc[c0 + 1]) + __ldg(&bc[64 + c0 + 1]), 0.f);
                    uint2 u;
                    u.x = f2tf32(v0 - mrow[c0] * minv);
                    u.y = f2tf32(v1 - mrow[c0 + 1] * minv);
                    *(uint2*)&XS2u[lr0 * XST + c0] = u;
                }
            } else {
#pragma unroll
                for (int nt = 0; nt < 8; nt++)
                    *(uint2*)&XS2u[lr0 * XST + nt * 8 + 2 * t] = make_uint2(0, 0);
            }
            if (r1 < p.nrows) {
                int c = cl[r1];
                float minv = 1.f / fmaxf(cnt[c], 1.f);
                const float* mrow = sum + (size_t)c * 64;
#pragma unroll
                for (int nt = 0; nt < 8; nt++) {
                    int c0 = nt * 8 + 2 * t;
                    float v2 = fmaxf(d[mt][nt][2] * __ldg(&bc[c0]) + __ldg(&bc[64 + c0]), 0.f);
                    float v3 = fmaxf(d[mt][nt][3] * __ldg(&bc[c0 + 1]) + __ldg(&bc[64 + c0 + 1]), 0.f);
                    uint2 u;
                    u.x = f2tf32(v2 - mrow[c0] * minv);
                    u.y = f2tf32(v3 - mrow[c0 + 1] * minv);
                    *(uint2*)&XS2u[lr1 * XST + c0] = u;
                }
            } else {
#pragma unroll
                for (int nt = 0; nt < 8; nt++)
                    *(uint2*)&XS2u[lr1 * XST + nt * 8 + 2 * t] = make_uint2(0, 0);
            }
        }
        __syncthreads();
        load_w_tile(WSu, p.Ww + s * 4096, tid);
        __syncthreads();
        zero_acc(d);
        mma_block(d, XS2u, WSu, w, g, t);

        float* out = outs[s];
        float* den = dens[s];
#pragma unroll
        for (int mt = 0; mt < 2; mt++) {
            int r0 = base + w * 32 + mt * 16 + g;
            int r1 = r0 + 8;
            if (r0 < p.nrows) {
                int c = cl[r0];
#pragma unroll
                for (int nt = 0; nt < 8; nt++) {
                    int c0 = nt * 8 + 2 * t;
                    float e0 = __expf(d[mt][nt][0]);
                    float e1 = __expf(d[mt][nt][1]);
                    *(float2*)(out + (size_t)r0 * 64 + c0) = make_float2(e0, e1);
                    red2(&den[(size_t)c * 64 + c0], e0, e1);
                }
            }
            if (r1 < p.nrows) {
                int c = cl[r1];
#pragma unroll
                for (int nt = 0; nt < 8; nt++) {
                    int c0 = nt * 8 + 2 * t;
                    float e2 = __expf(d[mt][nt][2]);
                    float e3 = __expf(d[mt][nt][3]);
                    *(float2*)(out + (size_t)r1 * 64 + c0) = make_float2(e2, e3);
                    red2(&den[(size_t)c * 64 + c0], e2, e3);
                }
            }
        }
    }
}

// ---------------------------------------------------------------------------
// projcomb (128 threads)
// ---------------------------------------------------------------------------
struct PJP {
    const float* X; const float* Wbase;
    const float* PW0; const float* PW1; const float* PW2;
    const float* dn0; const float* dn1; const float* dn2;
    float* pf0; float* pf1; float* pf2;
    const int* cl0; const int* cl1; const int* cl2;
    float* flast;
    const float* bnc;
    int nrows;
};

__global__ void __launch_bounds__(128) projcomb_k(PJP p)
{
    extern __shared__ float sm[];
    unsigned* XSu = (unsigned*)sm;
    unsigned* WSu = (unsigned*)(sm + SM_XS);

    const int tid  = threadIdx.x;
    const int base = blockIdx.x * 128;
    const int lane = tid & 31, w = tid >> 5, g = lane >> 2, t = lane & 3;

    load_x_plain(XSu, p.X, base, tid, p.nrows);

    const float* PWs[3] = {p.PW0, p.PW1, p.PW2};
    const float* dns[3] = {p.dn0, p.dn1, p.dn2};
    float* pfs[3] = {p.pf0, p.pf1, p.pf2};
    const int* cls[3] = {p.cl0, p.cl1, p.cl2};

    float d[2][8][4];
#pragma unroll
    for (int s = 0; s < 4; s++) {
        __syncthreads();
        load_w_tile(WSu, p.Wbase + s * 4096, tid);
        __syncthreads();
        zero_acc(d);
        mma_block(d, XSu, WSu, w, g, t);

        const float* bc = p.bnc + (3 + s) * 128;
        if (s < 3) {
            const float* PW = PWs[s];
            const float* dn = dns[s];
            float* pf = pfs[s];
            const int* cl = cls[s];
            int r0a[2], r1a[2], cr0a[2], cr1a[2];
#pragma unroll
            for (int mt = 0; mt < 2; mt++) {
                r0a[mt] = base + w * 32 + mt * 16 + g;
                r1a[mt] = r0a[mt] + 8;
                cr0a[mt] = (r0a[mt] < p.nrows) ? cl[r0a[mt]] : 0;
                cr1a[mt] = (r1a[mt] < p.nrows) ? cl[r1a[mt]] : 0;
            }
#pragma unroll
            for (int nt = 0; nt < 8; nt++) {
                int c0 = nt * 8 + 2 * t;
                float s0 = __ldg(&bc[c0]),      s1 = __ldg(&bc[c0 + 1]);
                float h0 = __ldg(&bc[64 + c0]), h1 = __ldg(&bc[64 + c0 + 1]);
#pragma unroll
                for (int mt = 0; mt < 2; mt++) {
                    if (r0a[mt] < p.nrows) {
                        float v0 = fmaxf(d[mt][nt][0] * s0 + h0, 0.f);
                        float v1 = fmaxf(d[mt][nt][1] * s1 + h1, 0.f);
                        float2 pw = *(const float2*)(PW + (size_t)r0a[mt] * 64 + c0);
                        float2 de = *(const float2*)(dn + (size_t)cr0a[mt] * 64 + c0);
                        red2(&pf[(size_t)cr0a[mt] * 64 + c0],
                             v0 * __fdividef(pw.x, de.x + 1e-6f),
                             v1 * __fdividef(pw.y, de.y + 1e-6f));
                    }
                    if (r1a[mt] < p.nrows) {
                        float v2 = fmaxf(d[mt][nt][2] * s0 + h0, 0.f);
                        float v3 = fmaxf(d[mt][nt][3] * s1 + h1, 0.f);
                        float2 pw = *(const float2*)(PW + (size_t)r1a[mt] * 64 + c0);
                        float2 de = *(const float2*)(dn + (size_t)cr1a[mt] * 64 + c0);
                        red2(&pf[(size_t)cr1a[mt] * 64 + c0],
                             v2 * __fdividef(pw.x, de.x + 1e-6f),
                             v3 * __fdividef(pw.y, de.y + 1e-6f));
                    }
                }
            }
        } else {
#pragma unroll
            for (int mt = 0; mt < 2; mt++) {
                int r0 = base + w * 32 + mt * 16 + g;
                int r1 = r0 + 8;
#pragma unroll
                for (int nt = 0; nt < 8; nt++) {
                    int c0 = nt * 8 + 2 * t;
                    float s0 = __ldg(&bc[c0]),      s1 = __ldg(&bc[c0 + 1]);
                    float h0 = __ldg(&bc[64 + c0]), h1 = __ldg(&bc[64 + c0 + 1]);
                    if (r0 < p.nrows)
                        *(float2*)(p.flast + (size_t)r0 * 64 + c0) =
                            make_float2(fmaxf(d[mt][nt][0] * s0 + h0, 0.f),
                                        fmaxf(d[mt][nt][1] * s1 + h1, 0.f));
                    if (r1 < p.nrows)
                        *(float2*)(p.flast + (size_t)r1 * 64 + c0) =
                            make_float2(fmaxf(d[mt][nt][2] * s0 + h0, 0.f),
                                        fmaxf(d[mt][nt][3] * s1 + h1, 0.f));
                }
            }
        }
    }
}

// ---------------------------------------------------------------------------
// fuse-gemm (128 threads)
// ---------------------------------------------------------------------------
struct FSP {
    const float* X; const float* W; float* Y;
    const float* adp;
    const int *cl0, *cl1, *cl2;
    const float *pf0, *pf1, *pf2;
    int nrows;
};

__global__ void __launch_bounds__(128) fusek(FSP p)
{
    extern __shared__ float sm[];
    unsigned* XSu = (unsigned*)sm;
    unsigned* WSu = (unsigned*)(sm + SM_XS);
    float* SSUM = sm + SM_XS + SM_WS;
    float* SSQ  = SSUM + 64;

    const int tid  = threadIdx.x;
    const int base = blockIdx.x * 128;
    const int lane = tid & 31, w = tid >> 5, g = lane >> 2, t = lane & 3;

    if (tid < 64) { SSUM[tid] = 0.f; SSQ[tid] = 0.f; }

    float d[2][8][4];
    zero_acc(d);

    for (int pp = 0; pp < 2; pp++) {
        __syncthreads();
        load_w_tile(WSu, p.W + pp * 4096, tid);
        int n = base + tid;
        if (n < p.nrows) {
            if (pp == 1) {
                float a0 = p.adp[(size_t)n * 3 + 0];
                float a1 = p.adp[(size_t)n * 3 + 1];
                float a2 = p.adp[(size_t)n * 3 + 2];
                const float4* q0 = (const float4*)(p.pf0 + (size_t)p.cl0[n] * 64);
                const float4* q1 = (const float4*)(p.pf1 + (size_t)p.cl1[n] * 64);
                const float4* q2 = (const float4*)(p.pf2 + (size_t)p.cl2[n] * 64);
#pragma unroll
                for (int c4 = 0; c4 < 16; c4++) {
                    float4 v0 = q0[c4], v1 = q1[c4], v2 = q2[c4];
                    uint4 u;
                    u.x = f2tf32(a0 * v0.x + a1 * v1.x + a2 * v2.x);
                    u.y = f2tf32(a0 * v0.y + a1 * v1.y + a2 * v2.y);
                    u.z = f2tf32(a0 * v0.z + a1 * v1.z + a2 * v2.z);
                    u.w = f2tf32(a0 * v0.w + a1 * v1.w + a2 * v2.w);
                    *(uint4*)&XSu[tid * XST + c4 * 4] = u;
                }
            } else {
                const float4* src = (const float4*)(p.X + (size_t)n * 64);
#pragma unroll
                for (int c4 = 0; c4 < 16; c4++) {
                    float4 v = src[c4];
                    uint4 u;
                    u.x = f2tf32(v.x); u.y = f2tf32(v.y);
                    u.z = f2tf32(v.z); u.w = f2tf32(v.w);
                    *(uint4*)&XSu[tid * XST + c4 * 4] = u;
                }
            }
        } else {
            uint4 z = make_uint4(0, 0, 0, 0);
#pragma unroll
            for (int c4 = 0; c4 < 16; c4++)
                *(uint4*)&XSu[tid * XST + c4 * 4] = z;
        }
        __syncthreads();
        mma_block(d, XSu, WSu, w, g, t);
    }
    __syncthreads();

#pragma unroll
    for (int mt = 0; mt < 2; mt++) {
        int r0 = base + w * 32 + mt * 16 + g;
        int r1 = r0 + 8;
#pragma unroll
        for (int nt = 0; nt < 8; nt++) {
            int c0 = nt * 8 + 2 * t;
            if (r0 < p.nrows)
                *(float2*)(p.Y + (size_t)r0 * 64 + c0) = make_float2(d[mt][nt][0], d[mt][nt][1]);
            if (r1 < p.nrows)
                *(float2*)(p.Y + (size_t)r1 * 64 + c0) = make_float2(d[mt][nt][2], d[mt][nt][3]);
        }
    }

#pragma unroll
    for (int nt = 0; nt < 8; nt++) {
        float s0 = 0.f, s1 = 0.f, q0 = 0.f, q1 = 0.f;
#pragma unroll
        for (int mt = 0; mt < 2; mt++) {
            int r0 = base + w * 32 + mt * 16 + g;
            if (r0 < p.nrows) {
                s0 += d[mt][nt][0]; q0 += d[mt][nt][0] * d[mt][nt][0];
                s1 += d[mt][nt][1]; q1 += d[mt][nt][1] * d[mt][nt][1];
            }
            if (r0 + 8 < p.nrows) {
                s0 += d[mt][nt][2]; q0 += d[mt][nt][2] * d[mt][nt][2];
                s1 += d[mt][nt][3]; q1 += d[mt][nt][3] * d[mt][nt][3];
            }
        }
        int c0 = nt * 8 + 2 * t;
        atomicAdd(&SSUM[c0], s0);     atomicAdd(&SSUM[c0 + 1], s1);
        atomicAdd(&SSQ[c0], q0);      atomicAdd(&SSQ[c0 + 1], q1);
    }
    __syncthreads();
    if (tid < 64) {
        atomicAdd(&g_stats[tid],      (double)SSUM[tid]);
        atomicAdd(&g_stats[64 + tid], (double)SSQ[tid]);
    }
}

// ---------------------------------------------------------------------------
// SYRK + bncoef + finalize
// ---------------------------------------------------------------------------
__global__ void __launch_bounds__(128) syrk_k(const float* __restrict__ X,
                                              float* __restrict__ S,
                                              float* __restrict__ M, int nrows)
{
    extern __shared__ float sm[];
    unsigned* XSu = (unsigned*)sm;
    const int tid  = threadIdx.x;
    const int base = blockIdx.x * 128;
    const int lane = tid & 31, w = tid >> 5, g = lane >> 2, t = lane & 3;

    load_x_plain(XSu, X, base, tid, nrows);
    __syncthreads();

    const int m0 = w * 16;
    float d[8][4];
#pragma unroll
    for (int nt = 0; nt < 8; nt++)
#pragma unroll
        for (int i = 0; i < 4; i++) d[nt][i] = 0.f;

#pragma unroll
    for (int kt = 0; kt < 16; kt++) {
        int k0 = kt * 8;
        unsigned a[4];
        a[0] = XSu[(k0 + t) * XST + m0 + g];
        a[1] = XSu[(k0 + t) * XST + m0 + g + 8];
        a[2] = XSu[(k0 + t + 4) * XST + m0 + g];
        a[3] = XSu[(k0 + t + 4) * XST + m0 + g + 8];
#pragma unroll
        for (int nt = 0; nt < 8; nt++) {
            unsigned b[2];
            b[0] = XSu[(k0 + t) * XST + nt * 8 + g];
            b[1] = XSu[(k0 + t + 4) * XST + nt * 8 + g];
            mma_tf32(d[nt], a, b);
        }
    }
#pragma unroll
    for (int nt = 0; nt < 8; nt++) {
        int c0 = nt * 8 + 2 * t;
        red2(&S[(m0 + g) * 64 + c0],     d[nt][0], d[nt][1]);
        red2(&S[(m0 + g + 8) * 64 + c0], d[nt][2], d[nt][3]);
    }
    if (tid < 64) {
        float s = 0.f;
        for (int r = 0; r < 128; r++)
            s += __uint_as_float(XSu[r * XST + tid]);
        atomicAdd(&M[tid], s);
    }
}

struct BC {
    const float* W[7];
    const float* gamma[7];
    const float* beta[7];
    float invN;
};

__global__ void bncoef_k(BC p, const float* __restrict__ S,
                         const float* __restrict__ M, float* __restrict__ bnc)
{
    __shared__ float Ss[4096];
    __shared__ float Ws[4096];
    __shared__ float ms[64];
    const int slot = blockIdx.x;
    const int j = threadIdx.x;
    const float* W = p.W[slot];
    for (int i = j; i < 4096; i += 64) {
        Ss[i] = S[i];
        Ws[i] = __uint_as_float(f2tf32(W[i]));
    }
    ms[j] = M[j];
    __syncthreads();

    float mu = 0.f, ex2 = 0.f;
    for (int c = 0; c < 64; c++) {
        float wc = Ws[c * 64 + j];
        mu += ms[c] * wc;
        float inner = 0.f;
        for (int c2 = 0; c2 < 64; c2++)
            inner += Ss[c * 64 + c2] * Ws[c2 * 64 + j];
        ex2 += wc * inner;
    }
    mu *= p.invN; ex2 *= p.invN;
    float var = ex2 - mu * mu;
    float rs = rsqrtf(var + 1e-3f);
    float scale = p.gamma[slot][j] * rs;
    bnc[slot * 128 + j]      = scale;
    bnc[slot * 128 + 64 + j] = p.beta[slot][j] - mu * scale;
}

__global__ void finalize_k(const float* __restrict__ gamma,
                           const float* __restrict__ beta, float invN)
{
    int c = threadIdx.x;
    float mu  = (float)g_stats[c] * invN;
    float ex2 = (float)g_stats[64 + c] * invN;
    float var = ex2 - mu * mu;
    float rs  = rsqrtf(var + 1e-3f);
    float scale = gamma[c] * rs;
    g_bnc[7 * 128 + c]      = scale;
    g_bnc[7 * 128 + 64 + c] = beta[c] - mu * scale;
    g_stats[c] = 0.0;
    g_stats[64 + c] = 0.0;
}

// ---------------------------------------------------------------------------
// Conv (256 threads, M/N warp split, depth-2 cp.async) — unchanged
// ---------------------------------------------------------------------------
__global__ void __launch_bounds__(256) conv27p(
    const float* __restrict__ F, const int* __restrict__ nbr,
    const float* __restrict__ Wc, float* __restrict__ Y, int nrows)
{
    extern __shared__ float sm[];
    float* XB0 = sm;
    float* XB1 = sm + CSM_X;
    float* WB0 = sm + 2 * CSM_X;
    float* WB1 = sm + 2 * CSM_X + CSM_W;
    float* SSUM = sm + 2 * CSM_X + 2 * CSM_W;
    float* SSQ  = SSUM + 64;

    const int tid  = threadIdx.x;
    const int base = blockIdx.x * 128;
    const int lane = tid & 31, wid = tid >> 5, g = lane >> 2, t = lane & 3;
    const int mrow0 = (wid & 3) * 32;
    const int nbase = (wid >> 2) * 32;

    const int xr = tid >> 1, xh = (tid & 1) * 32;
    const int xn = base + xr;
    const int wr = tid >> 2, wq = (tid & 3) * 16;

    if (tid < 64) { SSUM[tid] = 0.f; SSQ[tid] = 0.f; }

    float d[2][4][4];
    zero_acc4(d);

    auto prefetch = [&](int k, float* XB, float* WB) {
        const float* src = F;
        int sz = 0;
        if (xn < nrows) {
            int idx = __ldg(&nbr[(size_t)xn * KTAP + k]);
            src = F + (size_t)idx * 64 + xh;
            sz = 16;
        }
#pragma unroll
        for (int c4 = 0; c4 < 8; c4++)
            cpa16(XB + xr * XST + xh + c4 * 4, src + c4 * 4, sz);
        const float* ws = Wc + k * 4096 + wr * 64 + wq;
#pragma unroll
        for (int c4 = 0; c4 < 4; c4++)
            cpa16(WB + wr * XST + wq + c4 * 4, ws + c4 * 4, 16);
    };

    prefetch(0, XB0, WB0);
    cpa_commit();

    for (int k = 0; k < KTAP; k++) {
        float* XB = (k & 1) ? XB1 : XB0;
        float* WB = (k & 1) ? WB1 : WB0;
        if (k + 1 < KTAP) {
            prefetch(k + 1, (k & 1) ? XB0 : XB1, (k & 1) ? WB0 : WB1);
            cpa_commit();
            cpa_wait<1>();
        } else {
            cpa_wait<0>();
        }
        __syncthreads();
        mma_split(d, (const unsigned*)XB, (const unsigned*)WB, mrow0, nbase, g, t);
        __syncthreads();
    }

#pragma unroll
    for (int mt = 0; mt < 2; mt++) {
        int r0 = base + mrow0 + mt * 16 + g;
        int r1 = r0 + 8;
#pragma unroll
        for (int nt = 0; nt < 4; nt++) {
            int c0 = nbase + nt * 8 + 2 * t;
            if (r0 < nrows)
                *(float2*)(Y + (size_t)r0 * 64 + c0) = make_float2(d[mt][nt][0], d[mt][nt][1]);
            if (r1 < nrows)
                *(float2*)(Y + (size_t)r1 * 64 + c0) = make_float2(d[mt][nt][2], d[mt][nt][3]);
        }
    }
#pragma unroll
    for (int nt = 0; nt < 4; nt++) {
        float s0 = 0.f, s1 = 0.f, q0 = 0.f, q1 = 0.f;
#pragma unroll
        for (int mt = 0; mt < 2; mt++) {
            int r0 = base + mrow0 + mt * 16 + g;
            if (r0 < nrows) {
                s0 += d[mt][nt][0]; q0 += d[mt][nt][0] * d[mt][nt][0];
                s1 += d[mt][nt][1]; q1 += d[mt][nt][1] * d[mt][nt][1];
            }
            if (r0 + 8 < nrows) {
                s0 += d[mt][nt][2]; q0 += d[mt][nt][2] * d[mt][nt][2];
                s1 += d[mt][nt][3]; q1 += d[mt][nt][3] * d[mt][nt][3];
            }
        }
        int c0 = nbase + nt * 8 + 2 * t;
        atomicAdd(&SSUM[c0], s0);     atomicAdd(&SSUM[c0 + 1], s1);
        atomicAdd(&SSQ[c0], q0);      atomicAdd(&SSQ[c0 + 1], q1);
    }
    __syncthreads();
    if (tid < 64) {
        atomicAdd(&g_stats[tid],      (double)SSUM[tid]);
        atomicAdd(&g_stats[64 + tid], (double)SSQ[tid]);
    }
}

// ---------------------------------------------------------------------------
// Elementwise kernels
// ---------------------------------------------------------------------------
__global__ void init_k(float4* sum, float4* den, float4* pf, int n4,
                       float4* cnt, int nc4)
{
    int i = blockIdx.x * blockDim.x + threadIdx.x;
    float4 z = make_float4(0.f, 0.f, 0.f, 0.f);
    int stride = gridDim.x * blockDim.x;
    for (int j = i; j < n4; j += stride) { sum[j] = z; den[j] = z; pf[j] = z; }
    for (int j = i; j < nc4; j += stride) cnt[j] = z;
    if (i < 128) g_stats[i] = 0.0;
    if (i < 1024) ((float4*)g_S)[i] = z;
    if (i < 16)   ((float4*)g_m)[i] = z;
}

template <int OP>
__global__ void bnapply_f4(const float4* __restrict__ X,
                           const float4* __restrict__ add,
                           float4* __restrict__ out, int n)
{
    __shared__ float SC[64], SH[64];
    int tid = threadIdx.x;
    if (tid < 64) { SC[tid] = g_bnc[7 * 128 + tid]; SH[tid] = g_bnc[7 * 128 + 64 + tid]; }
    __syncthreads();
    int i = blockIdx.x * blockDim.x + tid;
    if (i >= n * 16) return;
    int c = (i & 15) * 4;
    float4 x = X[i];
    float4 y;
    y.x = x.x * SC[c]     + SH[c];
    y.y = x.y * SC[c + 1] + SH[c + 1];
    y.z = x.z * SC[c + 2] + SH[c + 2];
    y.w = x.w * SC[c + 3] + SH[c + 3];
    float4 o;
    if (OP == 0) {
        o.x = f2tf32f(fmaxf(y.x, 0.f)); o.y = f2tf32f(fmaxf(y.y, 0.f));
        o.z = f2tf32f(fmaxf(y.z, 0.f)); o.w = f2tf32f(fmaxf(y.w, 0.f));
    } else if (OP == 1) {
        float4 a = add[i];
        o.x = f2tf32f(fmaxf(y.x, 0.f) + a.x); o.y = f2tf32f(fmaxf(y.y, 0.f) + a.y);
        o.z = f2tf32f(fmaxf(y.z, 0.f) + a.z); o.w = f2tf32f(fmaxf(y.w, 0.f) + a.w);
    } else {
        float4 a = add[i];
        o.x = fmaxf(y.x + a.x, 0.f); o.y = fmaxf(y.y + a.y, 0.f);
        o.z = fmaxf(y.z + a.z, 0.f); o.w = fmaxf(y.w + a.w, 0.f);
    }
    out[i] = o;
}

// ---------------------------------------------------------------------------
// Host launcher
// ---------------------------------------------------------------------------
extern "C" void kernel_launch(void* const* d_in, const int* in_sizes, int n_in,
                              void* d_out, int out_size)
{
    const float* feat   = (const float*)d_in[0];
    const int*   cl0    = (const int*)d_in[1];
    const int*   cl1    = (const int*)d_in[2];
    const int*   cl2    = (const int*)d_in[3];
    const int*   nbr    = (const int*)d_in[4];
    const float* W_lw   = (const float*)d_in[5];
    const float* g_lw   = (const float*)d_in[6];
    const float* b_lw   = (const float*)d_in[7];
    const float* W_w    = (const float*)d_in[8];
    const float* W_proj = (const float*)d_in[9];
    const float* g_proj = (const float*)d_in[10];
    const float* b_proj = (const float*)d_in[11];
    const float* W_adp  = (const float*)d_in[12];
    const float* W_fuse = (const float*)d_in[13];
    const float* g_fuse = (const float*)d_in[14];
    const float* b_fuse = (const float*)d_in[15];
    const float* W_c1   = (const float*)d_in[16];
    const float* g_c1   = (const float*)d_in[17];
    const float* b_c1   = (const float*)d_in[18];
    const float* W_c2   = (const float*)d_in[19];
    const float* g_c2   = (const float*)d_in[20];
    const float* b_c2   = (const float*)d_in[21];

    const int   n    = in_sizes[0] / 64;
    const float invN = 1.f / (float)n;
    float* D = (float*)d_out;

    float *A, *B, *C, *sumA, *denA, *pfA, *cntA, *adpb, *Sg, *Mg, *bnc;
    cudaGetSymbolAddress((void**)&A,     g_bufA);
    cudaGetSymbolAddress((void**)&B,     g_bufB);
    cudaGetSymbolAddress((void**)&C,     g_bufC);
    cudaGetSymbolAddress((void**)&sumA,  g_sumA);
    cudaGetSymbolAddress((void**)&denA,  g_denA);
    cudaGetSymbolAddress((void**)&pfA,   g_pfA);
    cudaGetSymbolAddress((void**)&cntA,  g_cntA);
    cudaGetSymbolAddress((void**)&adpb,  g_adpw);
    cudaGetSymbolAddress((void**)&Sg,    g_S);
    cudaGetSymbolAddress((void**)&Mg,    g_m);
    cudaGetSymbolAddress((void**)&bnc,   g_bnc);

    float* sum_[3] = {sumA, sumA + (size_t)NC0 * 64, sumA + (size_t)(NC0 + NC1) * 64};
    float* den_[3] = {denA, denA + (size_t)NC0 * 64, denA + (size_t)(NC0 + NC1) * 64};
    float* pf_[3]  = {pfA,  pfA  + (size_t)NC0 * 64, pfA  + (size_t)(NC0 + NC1) * 64};
    float* cnt_[3] = {cntA, cntA + NC0, cntA + NC0 + NC1};

    cudaFuncSetAttribute(lwsum_k,    cudaFuncAttributeMaxDynamicSharedMemorySize, LWS_SM_BYTES);
    cudaFuncSetAttribute(t3comb_k,   cudaFuncAttributeMaxDynamicSharedMemorySize, T3_SM_BYTES);
    cudaFuncSetAttribute(projcomb_k, cudaFuncAttributeMaxDynamicSharedMemorySize, GEMM_SM_BYTES);
    cudaFuncSetAttribute(fusek,      cudaFuncAttributeMaxDynamicSharedMemorySize, GEMM_SM_BYTES);
    cudaFuncSetAttribute(syrk_k,     cudaFuncAttributeMaxDynamicSharedMemorySize, (SM_XS + 64) * 4);
    cudaFuncSetAttribute(conv27p,    cudaFuncAttributeMaxDynamicSharedMemorySize, CONV_SM_BYTES);

    const int GB = (n + 127) / 128;
    const int E4 = (n * 16 + 255) / 256;

    // 1. init scratch
    init_k<<<2048, 256>>>((float4*)sumA, (float4*)denA, (float4*)pfA,
                          NCT * 16, (float4*)cntA, NCT / 4);
    // 2. SYRK + BN coefficients
    syrk_k<<<GB, 128, (SM_XS + 64) * 4>>>(feat, Sg, Mg, n);
    {
        BC bc{};
        for (int i = 0; i < 3; i++) {
            bc.W[i] = W_lw + i * 4096;       bc.gamma[i] = g_lw + i * 64;       bc.beta[i] = b_lw + i * 64;
            bc.W[3 + i] = W_proj + i * 4096; bc.gamma[3 + i] = g_proj + i * 64; bc.beta[3 + i] = b_proj + i * 64;
        }
        bc.W[6] = W_proj + 3 * 4096; bc.gamma[6] = g_proj + 192; bc.beta[6] = b_proj + 192;
        bc.invN = invN;
        bncoef_k<<<7, 64>>>(bc, Sg, Mg, bnc);
    }

    // 3. lwsum
    {
        LWS p{};
        p.X = feat; p.Wbase = W_lw;
        p.Wadp = W_adp; p.adp = adpb;
        p.sc0 = sum_[0]; p.sc1 = sum_[1]; p.sc2 = sum_[2];
        p.cnt0 = cnt_[0]; p.cnt1 = cnt_[1]; p.cnt2 = cnt_[2];
        p.cl0 = cl0; p.cl1 = cl1; p.cl2 = cl2;
        p.bnc = bnc; p.nrows = n;
        lwsum_k<<<GB, 128, LWS_SM_BYTES>>>(p);
    }

    // 4. t3comb
    {
        T3P p{};
        p.X = feat; p.Wlw = W_lw; p.Ww = W_w; p.bnc = bnc;
        p.sum0 = sum_[0]; p.sum1 = sum_[1]; p.sum2 = sum_[2];
        p.cnt0 = cnt_[0]; p.cnt1 = cnt_[1]; p.cnt2 = cnt_[2];
        p.den0 = den_[0]; p.den1 = den_[1]; p.den2 = den_[2];
        p.out0 = B; p.out1 = C; p.out2 = D;
        p.cl0 = cl0; p.cl1 = cl1; p.cl2 = cl2;
        p.nrows = n;
        t3comb_k<<<GB, 128, T3_SM_BYTES>>>(p);
    }

    // 5. projcomb
    {
        PJP p{};
        p.X = feat; p.Wbase = W_proj;
        p.PW0 = B; p.PW1 = C; p.PW2 = D;
        p.dn0 = den_[0]; p.dn1 = den_[1]; p.dn2 = den_[2];
        p.pf0 = pf_[0]; p.pf1 = pf_[1]; p.pf2 = pf_[2];
        p.cl0 = cl0; p.cl1 = cl1; p.cl2 = cl2;
        p.flast = A; p.bnc = bnc; p.nrows = n;
        projcomb_k<<<GB, 128, GEMM_SM_BYTES>>>(p);
    }

    // 6. fuse
    {
        FSP p{};
        p.X = A; p.W = W_fuse; p.Y = B;
        p.adp = adpb;
        p.cl0 = cl0; p.cl1 = cl1; p.cl2 = cl2;
        p.pf0 = pf_[0]; p.pf1 = pf_[1]; p.pf2 = pf_[2];
        p.nrows = n;
        fusek<<<GB, 128, GEMM_SM_BYTES>>>(p);
    }
    finalize_k<<<1, 64>>>(g_fuse, b_fuse, invN);
    bnapply_f4<1><<<E4, 256>>>((const float4*)B, (const float4*)feat, (float4*)C, n);

    // 7. conv1 -> bn -> relu (tf32) -> B
    conv27p<<<GB, 256, CONV_SM_BYTES>>>(C, nbr, W_c1, A, n);
    finalize_k<<<1, 64>>>(g_c1, b_c1, invN);
    bnapply_f4<0><<<E4, 256>>>((const float4*)A, nullptr, (float4*)B, n);

    // 8. conv2 -> bn ; out = relu(h + fused)
    conv27p<<<GB, 256, CONV_SM_BYTES>>>(B, nbr, W_c2, A, n);
    finalize_k<<<1, 64>>>(g_c2, b_c2, invN);
    bnapply_f4<2><<<E4, 256>>>((const float4*)A, (const float4*)C, (float4*)D, n);
}